// round 7
// baseline (speedup 1.0000x reference)
#include <cuda_runtime.h>
#include <cstdint>

// Problem constants
#define T_STEPS 2048
#define BATCH   256
#define IN_DIM  64
#define HID     256

// Tiling: 16 row-groups x 8 j-CTAs = 128 CTAs, 512 threads each.
// Thread: kslice = lane&15 (16 floats of k), jw = lane>>4, jloc = warp*2+jw.
#define GROUPS   16
#define JCTAS    8
#define ROWS     16
#define JW       32
#define THREADS  512

// Device scratch
__device__ float g_hs[(size_t)T_STEPS * BATCH * HID];   // h trajectory [T][B][H]
__device__ float g_h[2][BATCH * HID];                   // double-buffered state
__device__ unsigned int g_arr[GROUPS * 32];             // per-group monotonic arrival counters

typedef unsigned long long ull;

// ---- packed fp32x2 helpers ----
__device__ __forceinline__ void fma2(ull& acc, ull a, ull b) {
    asm("fma.rn.f32x2 %0, %1, %2, %0;" : "+l"(acc) : "l"(a), "l"(b));
}
__device__ __forceinline__ float redpair(ull v) {
    float lo = __uint_as_float((unsigned int)(v & 0xffffffffULL));
    float hi = __uint_as_float((unsigned int)(v >> 32));
    return lo + hi;
}
__device__ __forceinline__ ull packf(float lo, float hi) {
    return (ull)__float_as_uint(lo) | ((ull)__float_as_uint(hi) << 32);
}
__device__ __forceinline__ float fast_sig(float x) {
    return __fdividef(1.f, 1.f + __expf(-x));
}
__device__ __forceinline__ float fast_tanh(float x) {
    float y;
    asm("tanh.approx.f32 %0, %1;" : "=f"(y) : "f"(x));
    return y;
}
__device__ __forceinline__ unsigned int ld_acq(const unsigned int* p) {
    unsigned int v;
    asm volatile("ld.acquire.gpu.global.u32 %0, [%1];" : "=r"(v) : "l"(p));
    return v;
}
__device__ __forceinline__ void red_release(unsigned int* p) {
    asm volatile("red.release.gpu.global.add.u32 [%0], %1;" :: "l"(p), "r"(1u) : "memory");
}
__device__ __forceinline__ uint32_t smem_u32(const void* p) {
    uint32_t a;
    asm("{ .reg .u64 t; cvta.to.shared.u64 t, %1; cvt.u32.u64 %0, t; }" : "=r"(a) : "l"(p));
    return a;
}
__device__ __forceinline__ void cp_async16(uint32_t saddr, const void* gaddr) {
    asm volatile("cp.async.cg.shared.global [%0], [%1], 16;" :: "r"(saddr), "l"(gaddr) : "memory");
}
__device__ __forceinline__ void cp_async_commit_wait() {
    asm volatile("cp.async.commit_group;" ::: "memory");
    asm volatile("cp.async.wait_group 0;" ::: "memory");
}

// =====================================================================
// Persistent recurrent kernel: 512 threads/CTA, 16-way k-split,
// register-resident weights (60 regs/thread), per-warp L2 sync.
// =====================================================================
__global__ void __launch_bounds__(THREADS, 1) k_rec(
    const float* __restrict__ input,   // [T][B][I]
    const float* __restrict__ hidden,  // [1][B][3]
    const float* __restrict__ W_dec,   // [H][3]
    const float* __restrict__ b_dec,   // [H]
    const float* __restrict__ W_ih,    // [3H][I]
    const float* __restrict__ W_hh,    // [3H][H]
    const float* __restrict__ b_ih,    // [3H]
    const float* __restrict__ b_hh)    // [3H]
{
    __shared__ float h_s[ROWS * HID];      // 16 KB, XOR-swizzled (16B-chunk granularity)
    __shared__ float x_s[ROWS * IN_DIM];   // 4 KB, linear

    const int tid = threadIdx.x;
    const int lane = tid & 31;
    const int warp = tid >> 5;            // 0..15
    const int kslice = lane & 15;         // k in [kslice*16, kslice*16+16)
    const int jw = lane >> 4;             // 0..1
    const int jloc = warp * 2 + jw;       // 0..31
    const int grp = blockIdx.x >> 3;      // row group
    const int jc = blockIdx.x & 7;
    const int rbase = grp * ROWS;
    const int jg = jc * JW + jloc;        // global hidden column

    unsigned int* my_arr = &g_arr[grp * 32];
    const uint32_t hs_base = smem_u32(h_s);

    // swizzled float offset of column jg within an h_s row
    const int jsw = (((jg >> 2) ^ ((jg >> 5) & 7)) << 2) + (jg & 3);

    // --- load weights into registers (packed f32x2): 16 k-floats per gate ---
    ull whr[8], whz[8], whn[8];
    ull wxr[2], wxz[2], wxn[2];
    {
        const float4* W4 = (const float4*)W_hh;   // row stride 64 float4
        #pragma unroll
        for (int c = 0; c < 4; c++) {
            float4 vr = __ldg(&W4[((size_t)(0 * HID + jg)) * 64 + kslice * 4 + c]);
            float4 vz = __ldg(&W4[((size_t)(1 * HID + jg)) * 64 + kslice * 4 + c]);
            float4 vn = __ldg(&W4[((size_t)(2 * HID + jg)) * 64 + kslice * 4 + c]);
            whr[2*c] = packf(vr.x, vr.y); whr[2*c+1] = packf(vr.z, vr.w);
            whz[2*c] = packf(vz.x, vz.y); whz[2*c+1] = packf(vz.z, vz.w);
            whn[2*c] = packf(vn.x, vn.y); whn[2*c+1] = packf(vn.z, vn.w);
        }
        const float4* X4 = (const float4*)W_ih;   // row stride 16 float4
        {
            float4 vr = __ldg(&X4[((size_t)(0 * HID + jg)) * 16 + kslice]);
            float4 vz = __ldg(&X4[((size_t)(1 * HID + jg)) * 16 + kslice]);
            float4 vn = __ldg(&X4[((size_t)(2 * HID + jg)) * 16 + kslice]);
            wxr[0] = packf(vr.x, vr.y); wxr[1] = packf(vr.z, vr.w);
            wxz[0] = packf(vz.x, vz.y); wxz[1] = packf(vz.z, vz.w);
            wxn[0] = packf(vn.x, vn.y); wxn[1] = packf(vn.z, vn.w);
        }
    }

    const float bsum_r = b_ih[jg]           + b_hh[jg];
    const float bsum_z = b_ih[HID + jg]     + b_hh[HID + jg];
    const float bx_n   = b_ih[2 * HID + jg];
    const float bh_n   = b_hh[2 * HID + jg];

    // --- h0: each CTA writes a 512-elem chunk of its own group's rows ---
    {
        int idx = blockIdx.x * 512 + tid;
        int b = idx >> 8;
        int j = idx & 255;
        g_h[0][idx] = b_dec[j]
                    + hidden[b * 3 + 0] * W_dec[j * 3 + 0]
                    + hidden[b * 3 + 1] * W_dec[j * 3 + 1]
                    + hidden[b * 3 + 2] * W_dec[j * 3 + 2];
    }
    __syncthreads();
    if (lane == 0) red_release(my_arr);   // 16 arrivals per CTA, 128 per group

    const int r0 = kslice;                // the single row this thread owns
    const int rp_own = r0 >> 1;           // which row-pair carries it
    const bool ownA = (r0 & 1) == 0;

    // x prefetch register: threads 0..255 own one float4 of the 16x64 tile
    const int xrow = tid >> 4, xchunk = tid & 15;
    const float4* xp = (const float4*)(input + ((size_t)(rbase + xrow)) * IN_DIM) + xchunk;
    float4 xr4;
    if (tid < 256) xr4 = __ldg(xp);       // input[0] -> used at s=1
    const size_t xstride4 = (size_t)BATCH * IN_DIM / 4;

    // ---------------- time-step loop ----------------
    for (int s = 0; s < T_STEPS; s++) {
        // per-warp wait: h(s) ready when counter >= 128*(s+1)
        if (lane == 0) {
            unsigned int target = 128u * (unsigned int)(s + 1);
            while (ld_acq(my_arr) < target) { }
        }
        __syncwarp();

        // stage h tile [16][256] from g_h[s&1] via cp.async (swizzled)
        {
            const float4* hsrc = (const float4*)(g_h[s & 1] + (size_t)rbase * HID);
            #pragma unroll
            for (int it = 0; it < 2; it++) {
                int idx = tid + it * 512;            // 0..1023
                int row = idx >> 6, c4 = idx & 63;
                int phys = c4 ^ ((c4 >> 3) & 7);
                cp_async16(hs_base + (uint32_t)((row * HID + phys * 4) * 4), hsrc + idx);
            }
        }
        // stage x tile [16][64] (xs[0]=0, xs[s]=input[s-1]); 256 threads x float4 = 1024 floats
        if (tid < 256) {
            if (s == 0) {
                *(float4*)(x_s + tid * 4) = make_float4(0.f, 0.f, 0.f, 0.f);
            } else {
                *(float4*)(x_s + tid * 4) = xr4;
            }
            if (s <= T_STEPS - 2)
                xr4 = __ldg(xp + (size_t)s * xstride4);
        }

        cp_async_commit_wait();
        __syncthreads();

        float sr, sz, sh, sx;   // this thread's owned-row sums

        #pragma unroll 1
        for (int rp = 0; rp < 8; rp++) {
            const float* hra = h_s + (2 * rp)     * HID;
            const float* hrb = h_s + (2 * rp + 1) * HID;
            const float* xra = x_s + (2 * rp)     * IN_DIM;
            const float* xrb = x_s + (2 * rp + 1) * IN_DIM;
            ull pra = 0, pza = 0, nha = 0, nxa = 0;
            ull prb = 0, pzb = 0, nhb = 0, nxb = 0;
            #pragma unroll
            for (int c = 0; c < 4; c++) {
                int c4 = kslice * 4 + c;
                int p = c4 ^ ((c4 >> 3) & 7);
                ulonglong2 ha = *(const ulonglong2*)(hra + p * 4);
                ulonglong2 hb = *(const ulonglong2*)(hrb + p * 4);
                fma2(pra, ha.x, whr[2*c]); fma2(pra, ha.y, whr[2*c+1]);
                fma2(pza, ha.x, whz[2*c]); fma2(pza, ha.y, whz[2*c+1]);
                fma2(nha, ha.x, whn[2*c]); fma2(nha, ha.y, whn[2*c+1]);
                fma2(prb, hb.x, whr[2*c]); fma2(prb, hb.y, whr[2*c+1]);
                fma2(pzb, hb.x, whz[2*c]); fma2(pzb, hb.y, whz[2*c+1]);
                fma2(nhb, hb.x, whn[2*c]); fma2(nhb, hb.y, whn[2*c+1]);
            }
            {
                ulonglong2 xa = *(const ulonglong2*)(xra + kslice * 4);
                ulonglong2 xb = *(const ulonglong2*)(xrb + kslice * 4);
                fma2(pra, xa.x, wxr[0]); fma2(pra, xa.y, wxr[1]);
                fma2(pza, xa.x, wxz[0]); fma2(pza, xa.y, wxz[1]);
                fma2(nxa, xa.x, wxn[0]); fma2(nxa, xa.y, wxn[1]);
                fma2(prb, xb.x, wxr[0]); fma2(prb, xb.y, wxr[1]);
                fma2(pzb, xb.x, wxz[0]); fma2(pzb, xb.y, wxz[1]);
                fma2(nxb, xb.x, wxn[0]); fma2(nxb, xb.y, wxn[1]);
            }
            float var = redpair(pra), vaz = redpair(pza), vah = redpair(nha), vax = redpair(nxa);
            float vbr = redpair(prb), vbz = redpair(pzb), vbh = redpair(nhb), vbx = redpair(nxb);
            #pragma unroll
            for (int m = 1; m <= 8; m <<= 1) {
                var += __shfl_xor_sync(0xffffffffu, var, m);
                vaz += __shfl_xor_sync(0xffffffffu, vaz, m);
                vah += __shfl_xor_sync(0xffffffffu, vah, m);
                vax += __shfl_xor_sync(0xffffffffu, vax, m);
                vbr += __shfl_xor_sync(0xffffffffu, vbr, m);
                vbz += __shfl_xor_sync(0xffffffffu, vbz, m);
                vbh += __shfl_xor_sync(0xffffffffu, vbh, m);
                vbx += __shfl_xor_sync(0xffffffffu, vbx, m);
            }
            if (rp == rp_own) {
                if (ownA) { sr = var; sz = vaz; sh = vah; sx = vax; }
                else      { sr = vbr; sz = vbz; sh = vbh; sx = vbx; }
            }
        }

        // --- gate math + state update: this thread owns row r0 at column jg ---
        {
            float hold = h_s[r0 * HID + jsw];
            float rg = fast_sig(sr + bsum_r);
            float zg = fast_sig(sz + bsum_z);
            float ng = fast_tanh(sx + bx_n + rg * (sh + bh_n));
            float hnew = zg * (hold - ng) + ng;
            g_h[(s & 1) ^ 1][(rbase + r0) * HID + jg] = hnew;
            g_hs[((size_t)s * BATCH + rbase + r0) * HID + jg] = hnew;
        }

        // per-warp arrive
        __syncwarp();
        if (lane == 0) red_release(my_arr);
    }

    // reset counter for next graph replay (one CTA per group)
    if (jc == 0 && tid == 0) {
        unsigned int fin = 128u * (unsigned int)(T_STEPS + 1);
        while (ld_acq(my_arr) < fin) { }
        *my_arr = 0u;
        __threadfence();
    }
}

// =====================================================================
// Output GEMM (proven R3 version): 64 rows x 64 o, K=256 in 4 chunks
// =====================================================================
#define XPITCH 68
__global__ void __launch_bounds__(256) k_out(
    const float* __restrict__ W_out,   // [I][H]
    const float* __restrict__ b_out,   // [I]
    float* __restrict__ out)           // [B][T][I]
{
    __shared__ float hs_s[64 * XPITCH];
    __shared__ float ws_s[64 * XPITCH];
    const int tid = threadIdx.x;
    const int tx = tid & 15, ty = tid >> 4;
    const size_t mbase = (size_t)blockIdx.x * 64;

    ull acc[4][4];
    #pragma unroll
    for (int ii = 0; ii < 4; ii++)
        #pragma unroll
        for (int jj = 0; jj < 4; jj++) acc[ii][jj] = 0ULL;

    for (int kc = 0; kc < 4; kc++) {
        const int kofs = kc * 64;
        for (int i = tid; i < 1024; i += 256) {
            int row = i >> 4, c = i & 15;
            float4 v = *(const float4*)(g_hs + (mbase + row) * HID + kofs + c * 4);
            *(float4*)(hs_s + row * XPITCH + c * 4) = v;
        }
        for (int i = tid; i < 1024; i += 256) {
            int row = i >> 4, c = i & 15;
            float4 v = *(const float4*)(W_out + (size_t)row * HID + kofs + c * 4);
            *(float4*)(ws_s + row * XPITCH + c * 4) = v;
        }
        __syncthreads();
        #pragma unroll
        for (int k4 = 0; k4 < 16; k4++) {
            ulonglong2 a[4], w[4];
            #pragma unroll
            for (int ii = 0; ii < 4; ii++)
                a[ii] = *(const ulonglong2*)(hs_s + (ty * 4 + ii) * XPITCH + k4 * 4);
            #pragma unroll
            for (int jj = 0; jj < 4; jj++)
                w[jj] = *(const ulonglong2*)(ws_s + (jj * 16 + tx) * XPITCH + k4 * 4);
            #pragma unroll
            for (int ii = 0; ii < 4; ii++)
                #pragma unroll
                for (int jj = 0; jj < 4; jj++) {
                    fma2(acc[ii][jj], a[ii].x, w[jj].x);
                    fma2(acc[ii][jj], a[ii].y, w[jj].y);
                }
        }
        __syncthreads();
    }

    #pragma unroll
    for (int ii = 0; ii < 4; ii++) {
        size_t m = mbase + ty * 4 + ii;
        size_t t = m >> 8;
        size_t b = m & 255;
        float* op = out + (b * T_STEPS + t) * IN_DIM;
        #pragma unroll
        for (int jj = 0; jj < 4; jj++) {
            int o = jj * 16 + tx;
            op[o] = redpair(acc[ii][jj]) + b_out[o];
        }
    }
}

extern "C" void kernel_launch(void* const* d_in, const int* in_sizes, int n_in,
                              void* d_out, int out_size)
{
    const float* input  = (const float*)d_in[0];
    const float* hidden = (const float*)d_in[1];
    const float* W_dec  = (const float*)d_in[2];
    const float* b_dec  = (const float*)d_in[3];
    const float* W_ih   = (const float*)d_in[4];
    const float* W_hh   = (const float*)d_in[5];
    const float* b_ih   = (const float*)d_in[6];
    const float* b_hh   = (const float*)d_in[7];
    const float* W_out  = (const float*)d_in[8];
    const float* b_out  = (const float*)d_in[9];
    float* out = (float*)d_out;

    k_rec<<<GROUPS * JCTAS, THREADS>>>(input, hidden, W_dec, b_dec,
                                       W_ih, W_hh, b_ih, b_hh);
    k_out<<<(T_STEPS * BATCH) / 64, 256>>>(W_out, b_out, out);
}

// round 8
// speedup vs baseline: 1.2421x; 1.2421x over previous
#include <cuda_runtime.h>
#include <cstdint>

// Problem constants
#define T_STEPS 2048
#define BATCH   256
#define IN_DIM  64
#define HID     256

// Tiling: 16 row-groups x 8 j-CTAs = 128 CTAs, 256 threads each.
#define GROUPS   16
#define JCTAS    8
#define ROWS     16
#define JW       32

// Device scratch
__device__ float g_hs[(size_t)T_STEPS * BATCH * HID];   // h trajectory [T][B][H]
__device__ float g_h[2][BATCH * HID];                   // double-buffered state
__device__ unsigned int g_arr[GROUPS * 32];             // per-group monotonic arrival counters

typedef unsigned long long ull;

// ---- packed fp32x2 helpers ----
__device__ __forceinline__ void fma2(ull& acc, ull a, ull b) {
    asm("fma.rn.f32x2 %0, %1, %2, %0;" : "+l"(acc) : "l"(a), "l"(b));
}
__device__ __forceinline__ float redpair(ull v) {
    float lo = __uint_as_float((unsigned int)(v & 0xffffffffULL));
    float hi = __uint_as_float((unsigned int)(v >> 32));
    return lo + hi;
}
__device__ __forceinline__ ull packf(float lo, float hi) {
    return (ull)__float_as_uint(lo) | ((ull)__float_as_uint(hi) << 32);
}
__device__ __forceinline__ float fast_sig(float x) {
    return __fdividef(1.f, 1.f + __expf(-x));
}
__device__ __forceinline__ float fast_tanh(float x) {
    float y;
    asm("tanh.approx.f32 %0, %1;" : "=f"(y) : "f"(x));
    return y;
}
__device__ __forceinline__ unsigned int ld_acq(const unsigned int* p) {
    unsigned int v;
    asm volatile("ld.acquire.gpu.global.u32 %0, [%1];" : "=r"(v) : "l"(p));
    return v;
}
__device__ __forceinline__ void red_release(unsigned int* p) {
    asm volatile("red.release.gpu.global.add.u32 [%0], %1;" :: "l"(p), "r"(1u) : "memory");
}
__device__ __forceinline__ uint32_t smem_u32(const void* p) {
    uint32_t a;
    asm("{ .reg .u64 t; cvta.to.shared.u64 t, %1; cvt.u32.u64 %0, t; }" : "=r"(a) : "l"(p));
    return a;
}
__device__ __forceinline__ void cp_async16(uint32_t saddr, const void* gaddr) {
    asm volatile("cp.async.cg.shared.global [%0], [%1], 16;" :: "r"(saddr), "l"(gaddr) : "memory");
}
__device__ __forceinline__ void cp_async_commit_wait() {
    asm volatile("cp.async.commit_group;" ::: "memory");
    asm volatile("cp.async.wait_group 0;" ::: "memory");
}

// Per-warp reduction scratch: [8 warps][4 jw][18 16B-chunks = 72 floats]
// row-gate layout within a jw block: float index = row*4 + gate (16 rows x 4 gates = 64, pad to 72)
#define RED_WSTRIDE 288   // floats per warp (4 * 72)
#define RED_JSTRIDE 72

// =====================================================================
// Persistent recurrent kernel: register-resident weights,
// tournament reduction (7 shfl / row-pair), per-warp L2 sync.
// =====================================================================
__global__ void __launch_bounds__(256, 1) k_rec(
    const float* __restrict__ input,   // [T][B][I]
    const float* __restrict__ hidden,  // [1][B][3]
    const float* __restrict__ W_dec,   // [H][3]
    const float* __restrict__ b_dec,   // [H]
    const float* __restrict__ W_ih,    // [3H][I]
    const float* __restrict__ W_hh,    // [3H][H]
    const float* __restrict__ b_ih,    // [3H]
    const float* __restrict__ b_hh)    // [3H]
{
    __shared__ float h_s[ROWS * HID];            // 16 KB, XOR-swizzled (16B-chunk)
    __shared__ float x_s[ROWS * IN_DIM];         // 4 KB
    __shared__ float red_s[8 * RED_WSTRIDE];     // 9 KB per-warp gate scratch

    const int tid = threadIdx.x;
    const int lane = tid & 31;
    const int warp = tid >> 5;
    const int kslice = lane & 7;          // k in [kslice*32, kslice*32+32)
    const int jw = lane >> 3;             // j within warp (0..3)
    const int jloc = warp * 4 + jw;       // 0..31
    const int grp = blockIdx.x >> 3;      // row group
    const int jc = blockIdx.x & 7;
    const int rbase = grp * ROWS;
    const int jg = jc * JW + jloc;        // global hidden column

    unsigned int* my_arr = &g_arr[grp * 32];
    const uint32_t hs_base = smem_u32(h_s);

    // swizzled float offset of column jg within an h_s row
    const int jsw = (((jg >> 2) ^ ((jg >> 5) & 7)) << 2) + (jg & 3);

    const bool bit2 = (kslice & 4) != 0;
    const bool bit1 = (kslice & 2) != 0;
    const bool bit0 = (kslice & 1) != 0;
    // tournament result of lane = value index kslice: row = 2rp + (kslice>>2), gate = kslice&3
    float* red_w = red_s + warp * RED_WSTRIDE + jw * RED_JSTRIDE;
    const int red_store_ofs = (kslice >> 2) * 4 + (kslice & 3);   // + 8*rp at use

    // --- load weights into registers (packed f32x2) ---
    ull whr[16], whz[16], whn[16];
    ull wxr[4],  wxz[4],  wxn[4];
    {
        const float4* W4 = (const float4*)W_hh;   // row stride 64 float4
        #pragma unroll
        for (int c = 0; c < 8; c++) {
            float4 vr = __ldg(&W4[((size_t)(0 * HID + jg)) * 64 + kslice * 8 + c]);
            float4 vz = __ldg(&W4[((size_t)(1 * HID + jg)) * 64 + kslice * 8 + c]);
            float4 vn = __ldg(&W4[((size_t)(2 * HID + jg)) * 64 + kslice * 8 + c]);
            whr[2*c] = packf(vr.x, vr.y); whr[2*c+1] = packf(vr.z, vr.w);
            whz[2*c] = packf(vz.x, vz.y); whz[2*c+1] = packf(vz.z, vz.w);
            whn[2*c] = packf(vn.x, vn.y); whn[2*c+1] = packf(vn.z, vn.w);
        }
        const float4* X4 = (const float4*)W_ih;   // row stride 16 float4
        #pragma unroll
        for (int c = 0; c < 2; c++) {
            float4 vr = __ldg(&X4[((size_t)(0 * HID + jg)) * 16 + kslice * 2 + c]);
            float4 vz = __ldg(&X4[((size_t)(1 * HID + jg)) * 16 + kslice * 2 + c]);
            float4 vn = __ldg(&X4[((size_t)(2 * HID + jg)) * 16 + kslice * 2 + c]);
            wxr[2*c] = packf(vr.x, vr.y); wxr[2*c+1] = packf(vr.z, vr.w);
            wxz[2*c] = packf(vz.x, vz.y); wxz[2*c+1] = packf(vz.z, vz.w);
            wxn[2*c] = packf(vn.x, vn.y); wxn[2*c+1] = packf(vn.z, vn.w);
        }
    }

    const float bsum_r = b_ih[jg]           + b_hh[jg];
    const float bsum_z = b_ih[HID + jg]     + b_hh[HID + jg];
    const float bx_n   = b_ih[2 * HID + jg];
    const float bh_n   = b_hh[2 * HID + jg];

    // --- h0: each CTA writes a 512-elem chunk of its own group's rows ---
    {
        int base = blockIdx.x * 512;
        for (int u = tid; u < 512; u += 256) {
            int idx = base + u;
            int b = idx >> 8;
            int j = idx & 255;
            g_h[0][idx] = b_dec[j]
                        + hidden[b * 3 + 0] * W_dec[j * 3 + 0]
                        + hidden[b * 3 + 1] * W_dec[j * 3 + 1]
                        + hidden[b * 3 + 2] * W_dec[j * 3 + 2];
        }
    }
    __syncthreads();
    if (lane == 0) red_release(my_arr);   // 8 arrivals per CTA, 64 per group

    const int r0 = kslice, r1 = kslice + 8;   // rows this thread owns for gate math

    // x prefetch register: thread owns one float4 of the 16x64 tile
    const int xrow = tid >> 4, xchunk = tid & 15;
    const float4* xp = (const float4*)(input + ((size_t)(rbase + xrow)) * IN_DIM) + xchunk;
    float4 xr4 = __ldg(xp);                       // input[0] -> used at s=1
    const size_t xstride4 = (size_t)BATCH * IN_DIM / 4;

    // ---------------- time-step loop ----------------
    for (int s = 0; s < T_STEPS; s++) {
        // per-warp wait: h(s) ready when counter >= 64*(s+1)
        if (lane == 0) {
            unsigned int target = 64u * (unsigned int)(s + 1);
            while (ld_acq(my_arr) < target) { }
        }
        __syncwarp();

        // stage h tile [16][256] from g_h[s&1] via cp.async (swizzled)
        {
            const float4* hsrc = (const float4*)(g_h[s & 1] + (size_t)rbase * HID);
            #pragma unroll
            for (int it = 0; it < 4; it++) {
                int idx = tid + it * 256;            // 0..1023
                int row = idx >> 6, c4 = idx & 63;
                int phys = c4 ^ ((c4 >> 3) & 7);
                cp_async16(hs_base + (uint32_t)((row * HID + phys * 4) * 4), hsrc + idx);
            }
        }
        // stage x tile [16][64] (xs[0]=0, xs[s]=input[s-1])
        if (s == 0) {
            *(float4*)(x_s + tid * 4) = make_float4(0.f, 0.f, 0.f, 0.f);
        } else {
            *(float4*)(x_s + tid * 4) = xr4;
        }
        if (s <= T_STEPS - 2)
            xr4 = __ldg(xp + (size_t)s * xstride4);

        cp_async_commit_wait();
        __syncthreads();

        #pragma unroll 1
        for (int rp = 0; rp < 8; rp++) {
            const float* hra = h_s + (2 * rp)     * HID;
            const float* hrb = h_s + (2 * rp + 1) * HID;
            const float* xra = x_s + (2 * rp)     * IN_DIM;
            const float* xrb = x_s + (2 * rp + 1) * IN_DIM;
            // value order: v0..3 = rowA (r, z, nh, nx), v4..7 = rowB
            ull acc0 = 0, acc1 = 0, acc2 = 0, acc3 = 0;
            ull acc4 = 0, acc5 = 0, acc6 = 0, acc7 = 0;
            #pragma unroll
            for (int c = 0; c < 8; c++) {
                int p = (kslice << 3) + (c ^ kslice);
                ulonglong2 ha = *(const ulonglong2*)(hra + p * 4);
                ulonglong2 hb = *(const ulonglong2*)(hrb + p * 4);
                fma2(acc0, ha.x, whr[2*c]); fma2(acc0, ha.y, whr[2*c+1]);
                fma2(acc1, ha.x, whz[2*c]); fma2(acc1, ha.y, whz[2*c+1]);
                fma2(acc2, ha.x, whn[2*c]); fma2(acc2, ha.y, whn[2*c+1]);
                fma2(acc4, hb.x, whr[2*c]); fma2(acc4, hb.y, whr[2*c+1]);
                fma2(acc5, hb.x, whz[2*c]); fma2(acc5, hb.y, whz[2*c+1]);
                fma2(acc6, hb.x, whn[2*c]); fma2(acc6, hb.y, whn[2*c+1]);
            }
            #pragma unroll
            for (int c = 0; c < 2; c++) {
                ulonglong2 xa = *(const ulonglong2*)(xra + (kslice * 2 + c) * 4);
                ulonglong2 xb = *(const ulonglong2*)(xrb + (kslice * 2 + c) * 4);
                fma2(acc0, xa.x, wxr[2*c]); fma2(acc0, xa.y, wxr[2*c+1]);
                fma2(acc1, xa.x, wxz[2*c]); fma2(acc1, xa.y, wxz[2*c+1]);
                fma2(acc3, xa.x, wxn[2*c]); fma2(acc3, xa.y, wxn[2*c+1]);
                fma2(acc4, xb.x, wxr[2*c]); fma2(acc4, xb.y, wxr[2*c+1]);
                fma2(acc5, xb.x, wxz[2*c]); fma2(acc5, xb.y, wxz[2*c+1]);
                fma2(acc7, xb.x, wxn[2*c]); fma2(acc7, xb.y, wxn[2*c+1]);
            }
            float v0 = redpair(acc0), v1 = redpair(acc1), v2 = redpair(acc2), v3 = redpair(acc3);
            float v4 = redpair(acc4), v5 = redpair(acc5), v6 = redpair(acc6), v7 = redpair(acc7);

            // tournament reduction over 8 k-lanes: 7 shfl, lane k ends with value k
            float w0, w1, w2, w3;
            {
                float t, r;
                t = bit2 ? v0 : v4; r = __shfl_xor_sync(0xffffffffu, t, 4); w0 = (bit2 ? v4 : v0) + r;
                t = bit2 ? v1 : v5; r = __shfl_xor_sync(0xffffffffu, t, 4); w1 = (bit2 ? v5 : v1) + r;
                t = bit2 ? v2 : v6; r = __shfl_xor_sync(0xffffffffu, t, 4); w2 = (bit2 ? v6 : v2) + r;
                t = bit2 ? v3 : v7; r = __shfl_xor_sync(0xffffffffu, t, 4); w3 = (bit2 ? v7 : v3) + r;
            }
            float u0, u1;
            {
                float t, r;
                t = bit1 ? w0 : w2; r = __shfl_xor_sync(0xffffffffu, t, 2); u0 = (bit1 ? w2 : w0) + r;
                t = bit1 ? w1 : w3; r = __shfl_xor_sync(0xffffffffu, t, 2); u1 = (bit1 ? w3 : w1) + r;
            }
            float fin;
            {
                float t = bit0 ? u0 : u1;
                float r = __shfl_xor_sync(0xffffffffu, t, 1);
                fin = (bit0 ? u1 : u0) + r;
            }
            red_w[rp * 8 + red_store_ofs] = fin;
        }
        __syncwarp();

        // --- gate math + state update: this thread owns rows r0, r1 at column jg ---
        float4 ga = *(const float4*)(red_w + r0 * 4);   // r, z, nh, nx for row r0
        float4 gb = *(const float4*)(red_w + r1 * 4);   // for row r1
        float* hnxt = g_h[(s & 1) ^ 1];
        float hna, hnb;
        {
            float hold = h_s[r0 * HID + jsw];
            float rg = fast_sig(ga.x + bsum_r);
            float zg = fast_sig(ga.y + bsum_z);
            float ng = fast_tanh(ga.w + bx_n + rg * (ga.z + bh_n));
            hna = zg * (hold - ng) + ng;
            hnxt[(rbase + r0) * HID + jg] = hna;
        }
        {
            float hold = h_s[r1 * HID + jsw];
            float rg = fast_sig(gb.x + bsum_r);
            float zg = fast_sig(gb.y + bsum_z);
            float ng = fast_tanh(gb.w + bx_n + rg * (gb.z + bh_n));
            hnb = zg * (hold - ng) + ng;
            hnxt[(rbase + r1) * HID + jg] = hnb;
        }

        // release FIRST (critical path), then trajectory stores (off-path)
        __syncwarp();
        if (lane == 0) red_release(my_arr);
        g_hs[((size_t)s * BATCH + rbase + r0) * HID + jg] = hna;
        g_hs[((size_t)s * BATCH + rbase + r1) * HID + jg] = hnb;
    }

    // reset counter for next graph replay (one CTA per group)
    if (jc == 0 && tid == 0) {
        unsigned int fin = 64u * (unsigned int)(T_STEPS + 1);
        while (ld_acq(my_arr) < fin) { }
        *my_arr = 0u;
        __threadfence();
    }
}

// =====================================================================
// Output GEMM (proven R3 version): 64 rows x 64 o, K=256 in 4 chunks
// =====================================================================
#define XPITCH 68
__global__ void __launch_bounds__(256) k_out(
    const float* __restrict__ W_out,   // [I][H]
    const float* __restrict__ b_out,   // [I]
    float* __restrict__ out)           // [B][T][I]
{
    __shared__ float hs_s[64 * XPITCH];
    __shared__ float ws_s[64 * XPITCH];
    const int tid = threadIdx.x;
    const int tx = tid & 15, ty = tid >> 4;
    const size_t mbase = (size_t)blockIdx.x * 64;

    ull acc[4][4];
    #pragma unroll
    for (int ii = 0; ii < 4; ii++)
        #pragma unroll
        for (int jj = 0; jj < 4; jj++) acc[ii][jj] = 0ULL;

    for (int kc = 0; kc < 4; kc++) {
        const int kofs = kc * 64;
        for (int i = tid; i < 1024; i += 256) {
            int row = i >> 4, c = i & 15;
            float4 v = *(const float4*)(g_hs + (mbase + row) * HID + kofs + c * 4);
            *(float4*)(hs_s + row * XPITCH + c * 4) = v;
        }
        for (int i = tid; i < 1024; i += 256) {
            int row = i >> 4, c = i & 15;
            float4 v = *(const float4*)(W_out + (size_t)row * HID + kofs + c * 4);
            *(float4*)(ws_s + row * XPITCH + c * 4) = v;
        }
        __syncthreads();
        #pragma unroll
        for (int k4 = 0; k4 < 16; k4++) {
            ulonglong2 a[4], w[4];
            #pragma unroll
            for (int ii = 0; ii < 4; ii++)
                a[ii] = *(const ulonglong2*)(hs_s + (ty * 4 + ii) * XPITCH + k4 * 4);
            #pragma unroll
            for (int jj = 0; jj < 4; jj++)
                w[jj] = *(const ulonglong2*)(ws_s + (jj * 16 + tx) * XPITCH + k4 * 4);
            #pragma unroll
            for (int ii = 0; ii < 4; ii++)
                #pragma unroll
                for (int jj = 0; jj < 4; jj++) {
                    fma2(acc[ii][jj], a[ii].x, w[jj].x);
                    fma2(acc[ii][jj], a[ii].y, w[jj].y);
                }
        }
        __syncthreads();
    }

    #pragma unroll
    for (int ii = 0; ii < 4; ii++) {
        size_t m = mbase + ty * 4 + ii;
        size_t t = m >> 8;
        size_t b = m & 255;
        float* op = out + (b * T_STEPS + t) * IN_DIM;
        #pragma unroll
        for (int jj = 0; jj < 4; jj++) {
            int o = jj * 16 + tx;
            op[o] = redpair(acc[ii][jj]) + b_out[o];
        }
    }
}

extern "C" void kernel_launch(void* const* d_in, const int* in_sizes, int n_in,
                              void* d_out, int out_size)
{
    const float* input  = (const float*)d_in[0];
    const float* hidden = (const float*)d_in[1];
    const float* W_dec  = (const float*)d_in[2];
    const float* b_dec  = (const float*)d_in[3];
    const float* W_ih   = (const float*)d_in[4];
    const float* W_hh   = (const float*)d_in[5];
    const float* b_ih   = (const float*)d_in[6];
    const float* b_hh   = (const float*)d_in[7];
    const float* W_out  = (const float*)d_in[8];
    const float* b_out  = (const float*)d_in[9];
    float* out = (float*)d_out;

    k_rec<<<GROUPS * JCTAS, 256>>>(input, hidden, W_dec, b_dec,
                                   W_ih, W_hh, b_ih, b_hh);
    k_out<<<(T_STEPS * BATCH) / 64, 256>>>(W_out, b_out, out);
}